// round 16
// baseline (speedup 1.0000x reference)
#include <cuda_runtime.h>
#include <cuda_bf16.h>
#include <cuda_fp16.h>
#include <math.h>
#include <stdint.h>

#define BB   4
#define NT   2304      // 48*48 tokens
#define CD   256       // DIM
#define AGH  512       // agent hidden
#define NH   4
#define DH   64

// plane sizes (elements)
#define XCAT_PLANE ((size_t)BB*NT*512)
#define XN_PLANE   ((size_t)2*BB*NT*CD)
#define ATT_PLANE  ((size_t)2*BB*NT*CD)
#define HID_PLANE  ((size_t)2*BB*NT*1024)
#define QKV_PLANE  ((size_t)2*BB*NT*768)

// ---------------- HMMA m16n8k16 fp16 ----------------
__device__ __forceinline__ void mma16816h(float* c, const uint32_t* a, uint32_t b0, uint32_t b1) {
    asm volatile("mma.sync.aligned.m16n8k16.row.col.f32.f16.f16.f32 "
        "{%0,%1,%2,%3}, {%4,%5,%6,%7}, {%8,%9}, {%0,%1,%2,%3};"
        : "+f"(c[0]), "+f"(c[1]), "+f"(c[2]), "+f"(c[3])
        : "r"(a[0]), "r"(a[1]), "r"(a[2]), "r"(a[3]), "r"(b0), "r"(b1));
}

__device__ __forceinline__ uint32_t smem_u32(const void* p) {
    uint32_t a;
    asm("{ .reg .u64 t; cvta.to.shared.u64 t, %1; cvt.u32.u64 %0, t; }" : "=r"(a) : "l"(p));
    return a;
}
#define CP16(dst, src) asm volatile("cp.async.cg.shared.global [%0], [%1], 16;" :: "r"(dst), "l"(src))
#define CP16P(dst, src, p) asm volatile("cp.async.cg.shared.global [%0], [%1], 16, %2;" :: "r"(dst), "l"(src), "r"((p)?16:0))
#define CPCOMMIT()     asm volatile("cp.async.commit_group;" ::: "memory")
#define CPWAIT(n)      asm volatile("cp.async.wait_group %0;" :: "n"(n) : "memory")
#define LDSM4(r, a) asm volatile("ldmatrix.sync.aligned.m8n8.x4.shared.b16 {%0,%1,%2,%3}, [%4];" \
    : "=r"((r)[0]), "=r"((r)[1]), "=r"((r)[2]), "=r"((r)[3]) : "r"(a))
#define LDSM4T(r, a) asm volatile("ldmatrix.sync.aligned.m8n8.x4.trans.shared.b16 {%0,%1,%2,%3}, [%4];" \
    : "=r"((r)[0]), "=r"((r)[1]), "=r"((r)[2]), "=r"((r)[3]) : "r"(a))

// fp16 helpers
__device__ __forceinline__ uint32_t packh2(float a, float b) {
    __half2 h2 = __floats2half2_rn(a, b);
    return *reinterpret_cast<uint32_t*>(&h2);
}
__device__ __forceinline__ void pack_hl2h(float a, float b, uint32_t& ph, uint32_t& pl) {
    __half ha = __float2half_rn(a), hb = __float2half_rn(b);
    float la = a - __half2float(ha), lb = b - __half2float(hb);
    ph = ((uint32_t)__half_as_ushort(hb)<<16)|(uint32_t)__half_as_ushort(ha);
    pl = ((uint32_t)__half_as_ushort(__float2half_rn(lb))<<16)
       | (uint32_t)__half_as_ushort(__float2half_rn(la));
}

// ---------------- scratch ----------------
__device__ float g_xcat[(size_t)BB*NT*512];
__device__ float g_part[(size_t)BB*NT*4];
__device__ float g_logits[BB*NT];
__device__ float g_maskf [BB*NT];
__device__ int   g_list[BB*NT];
__device__ int   g_iinv[BB*NT];
__device__ int   g_cnt [BB];
__device__ float g_x  [(size_t)2*BB*NT*CD];
__device__ __align__(16) __half g_xcat_h[XCAT_PLANE];
__device__ __align__(16) __half g_wag16 [2*262144];        // agent aw1 hi/lo fp16
__device__ __align__(16) __half g_w16  [1572864];          // mixer weights hi only
__device__ __align__(16) __half g_xn_h [XN_PLANE];
__device__ __align__(16) __half g_att_h[ATT_PLANE];
__device__ __align__(16) __half g_hid_h[HID_PLANE];
__device__ __align__(16) __half g_qkv_h[QKV_PLANE];

// ---------------- weight converts ----------------
__global__ void conv_wag16(const float* __restrict__ src, __half* __restrict__ dst, int n)
{
    __half* dh = dst;
    __half* dl = dst + n;
    int n4 = n >> 2;
    for (int i = blockIdx.x*256 + threadIdx.x; i < n4; i += gridDim.x*256) {
        float4 v = ((const float4*)src)[i];
        uint32_t h0,l0,h1,l1;
        pack_hl2h(v.x, v.y, h0, l0);
        pack_hl2h(v.z, v.w, h1, l1);
        *(uint2*)&dh[i*4] = make_uint2(h0, h1);
        *(uint2*)&dl[i*4] = make_uint2(l0, l1);
    }
}
struct W8 { const float* src[8]; int start[8]; int n[8]; };
__global__ void conv_w16(W8 a, __half* __restrict__ dst)
{
    int w = blockIdx.y;
    int n = a.n[w];
    const float4* s = (const float4*)a.src[w];
    __half* dh = dst + a.start[w];
    int n4 = n >> 2;
    for (int i = blockIdx.x*256 + threadIdx.x; i < n4; i += gridDim.x*256) {
        float4 v = s[i];
        *(uint2*)&dh[i*4] = make_uint2(packh2(v.x, v.y), packh2(v.z, v.w));
    }
}

// ---------------- transpose [B,C,N] -> token-major concat fp32 + fp16 ----------------
__global__ void transpose_cat(const float* __restrict__ fir, const float* __restrict__ fvis,
                              float* __restrict__ xcat, __half* __restrict__ xcat_h)
{
    int src = blockIdx.z & 1;
    int b   = blockIdx.z >> 1;
    const float* f = src ? fvis : fir;
    __shared__ float tile[32][33];
    int n0 = blockIdx.x * 32, c0 = blockIdx.y * 32;
    int tx = threadIdx.x, ty = threadIdx.y;
    #pragma unroll
    for (int i = 0; i < 32; i += 8)
        tile[ty + i][tx] = f[((size_t)b*CD + c0 + ty + i)*NT + n0 + tx];
    __syncthreads();
    #pragma unroll
    for (int i = 0; i < 32; i += 8) {
        float v = tile[tx][ty + i];
        size_t idx = ((size_t)b*NT + n0 + ty + i)*512 + src*CD + c0 + tx;
        xcat[idx] = v;
        xcat_h[idx] = __float2half_rn(v);
    }
}

#define RSB   80
#define MATB  (128*RSB)

__device__ __forceinline__ float actf(float t, int act) {
    if (act == 1) return t / (1.f + expf(-t));
    if (act == 2) return 0.5f*t*(1.f + erff(t*0.70710678118654752f));
    return t;
}

// ======= agent GEMM: fp16 2-term (A hi, W hi+lo), logit partial epilogue =======
#define AG_STG (3*MATB)
#define AGEMM_SMEM (3*AG_STG)   // 92160
__global__ void __launch_bounds__(256, 2)
gemm_agent16(const __half* __restrict__ Ah, const __half* __restrict__ Whl, size_t wplane,
             const float* __restrict__ bias,
             const float* __restrict__ logit_w, float* __restrict__ part)
{
    const int K = 512;
    int b = blockIdx.z;
    int m0 = blockIdx.y * 128;
    int o0 = blockIdx.x * 128;
    size_t rowbase = (size_t)b * NT;
    const __half* Ah_g = Ah + (rowbase + m0) * K;
    const __half* Wh_g = Whl + (size_t)o0 * K;
    const __half* Wl_g = Wh_g + wplane;

    extern __shared__ char smem[];
    uint32_t sbase = smem_u32(smem);
    int tid = threadIdx.x, lane = tid & 31, w = tid >> 5;
    int wm = w & 1, wn = w >> 1;          // 2 m-warps (64 rows) x 4 n-warps (32 cols)
    int gid = lane >> 2, tig = lane & 3;

    float acc[4][4][4];
    #pragma unroll
    for (int mt=0; mt<4; mt++)
        #pragma unroll
        for (int nt=0; nt<4; nt++)
            #pragma unroll
            for (int q=0; q<4; q++) acc[mt][nt][q] = 0.f;

#define PREFAG(cc, st) do { \
    uint32_t sb_ = sbase + (st)*AG_STG; \
    _Pragma("unroll") \
    for (int i_ = 0; i_ < 6; i_++) { \
        int f_ = tid + i_*256; int mat_ = f_ >> 9; int rem_ = f_ & 511; \
        int row_ = rem_ >> 2; int jb_ = (rem_ & 3) * 16; \
        const char* p_ = (mat_ == 0) ? (const char*)(Ah_g + (size_t)row_*K + (size_t)(cc)*32) \
                       : (mat_ == 1) ? (const char*)(Wh_g + (size_t)row_*K + (size_t)(cc)*32) \
                                     : (const char*)(Wl_g + (size_t)row_*K + (size_t)(cc)*32); \
        CP16(sb_ + (uint32_t)(mat_*MATB + row_*RSB + jb_), p_ + jb_); \
    } } while (0)

    int nchunk = K >> 5;  // 16
    PREFAG(0, 0);
    CPCOMMIT();
    PREFAG(1, 1);
    CPCOMMIT();

    for (int c = 0; c < nchunk; c++) {
        if (c == nchunk - 1) { CPWAIT(0); } else { CPWAIT(1); }
        __syncthreads();
        uint32_t stg = sbase + (c % 3) * AG_STG;
        #pragma unroll
        for (int ks = 0; ks < 2; ks++) {
            uint32_t colb = (uint32_t)(ks*32 + ((lane >> 4) << 4));
            uint32_t Ahf[4][4];
            #pragma unroll
            for (int mt = 0; mt < 4; mt++) {
                uint32_t sa = stg + (uint32_t)((wm*64 + mt*16 + (lane & 15)) * RSB) + colb;
                LDSM4(Ahf[mt], sa);
            }
            #pragma unroll
            for (int np = 0; np < 2; np++) {
                uint32_t sb = stg + MATB + (uint32_t)((wn*32 + np*16 + (lane & 15)) * RSB) + colb;
                uint32_t Bh[4], Bl[4];
                LDSM4(Bh, sb);
                LDSM4(Bl, sb + MATB);
                #pragma unroll
                for (int mt = 0; mt < 4; mt++) {
                    mma16816h(acc[mt][2*np],   Ahf[mt], Bh[0], Bh[2]);
                    mma16816h(acc[mt][2*np+1], Ahf[mt], Bh[1], Bh[3]);
                }
                #pragma unroll
                for (int mt = 0; mt < 4; mt++) {
                    mma16816h(acc[mt][2*np],   Ahf[mt], Bl[0], Bl[2]);
                    mma16816h(acc[mt][2*np+1], Ahf[mt], Bl[1], Bl[3]);
                }
            }
        }
        if (c + 2 < nchunk) { PREFAG(c+2, (c+2) % 3); CPCOMMIT(); }
    }
#undef PREFAG

    // logit partials: pr over this warp's 32 cols, rows wm*64 + mt*16 + gid (+8)
    float pr[8];
    #pragma unroll
    for (int i = 0; i < 8; i++) pr[i] = 0.f;
    #pragma unroll
    for (int mt = 0; mt < 4; mt++) {
        #pragma unroll
        for (int nt = 0; nt < 4; nt++) {
            int col = o0 + wn*32 + nt*8 + 2*tig;
            float b0v = bias[col], b1v = bias[col+1];
            float w0 = logit_w[col], w1 = logit_w[col+1];
            float t0 = actf(acc[mt][nt][0] + b0v, 1);
            float t1 = actf(acc[mt][nt][1] + b1v, 1);
            float t2 = actf(acc[mt][nt][2] + b0v, 1);
            float t3 = actf(acc[mt][nt][3] + b1v, 1);
            pr[2*mt+0] += t0*w0 + t1*w1;
            pr[2*mt+1] += t2*w0 + t3*w1;
        }
    }
    #pragma unroll
    for (int i = 0; i < 8; i++) {
        pr[i] += __shfl_xor_sync(0xffffffffu, pr[i], 1);
        pr[i] += __shfl_xor_sync(0xffffffffu, pr[i], 2);
    }
    __syncthreads();          // done with smem stages
    float* red = (float*)smem;  // [4 wn][128 rows]
    if (tig == 0) {
        #pragma unroll
        for (int mt = 0; mt < 4; mt++) {
            red[wn*128 + wm*64 + mt*16 + gid]     = pr[2*mt+0];
            red[wn*128 + wm*64 + mt*16 + gid + 8] = pr[2*mt+1];
        }
    }
    __syncthreads();
    if (tid < 128)
        part[((size_t)b*NT + m0 + tid)*4 + blockIdx.x] =
            (red[tid] + red[128 + tid]) + (red[256 + tid] + red[384 + tid]);
}

// ---------------- repair: finalize logits; fp32 recompute for near-zero ones ----------------
#define REPAIR_TAU 5e-3f
__global__ void repair(const float* __restrict__ part, const float* __restrict__ ab2,
                       const float* __restrict__ xcat,
                       const float* __restrict__ aw1, const float* __restrict__ ab1,
                       const float* __restrict__ aw2, float* __restrict__ logits)
{
    int b = blockIdx.y, t = blockIdx.x;
    int tid = threadIdx.x;
    __shared__ float l_sh;
    if (tid == 0) {
        size_t t4 = ((size_t)b*NT + t)*4;
        l_sh = ((part[t4] + part[t4+1]) + (part[t4+2] + part[t4+3])) + ab2[0];
    }
    __syncthreads();
    float lg = l_sh;
    if (fabsf(lg) >= REPAIR_TAU) {
        if (tid == 0) logits[b*NT + t] = lg;
        return;
    }
    // exact fp32 recompute (deterministic fixed-order)
    __shared__ float xs[512];
    const float* xr = xcat + ((size_t)b*NT + t)*512;
    for (int i = tid; i < 512; i += 256) xs[i] = xr[i];
    __syncthreads();
    float accv = 0.f;
    #pragma unroll
    for (int jj = 0; jj < 2; jj++) {
        int j = tid*2 + jj;
        const float* wr = aw1 + (size_t)j*512;
        float s = 0.f;
        for (int k = 0; k < 512; k++) s = fmaf(xs[k], wr[k], s);
        s += ab1[j];
        float h = s / (1.f + expf(-s));
        accv += h * aw2[j];
    }
    __shared__ float contrib[256];
    contrib[tid] = accv;
    __syncthreads();
    if (tid == 0) {
        float tot = 0.f;
        for (int i = 0; i < 256; i++) tot += contrib[i];
        logits[b*NT + t] = tot + ab2[0];
    }
}

// ======= fp16 single-term GEMM (W hi only), BMT x 128 block, 3-stage, 2 CTAs/SM =======
template<int BMT>
__global__ void __launch_bounds__(256, 2)
gemm_f16(const __half* __restrict__ Aall,
         const __half* __restrict__ Wah, const __half* __restrict__ Wbh,
         const float* __restrict__ ba, const float* __restrict__ bbv,
         float* __restrict__ Cf, __half* __restrict__ Ch,
         const float* __restrict__ R,
         const int* __restrict__ counts, int K, int Ocols, int act)
{
    constexpr int NWM   = 2;
    constexpr int WMEXT = BMT / NWM;
    constexpr int MT    = WMEXT / 16;
    constexpr int AMATB = BMT * RSB;
    constexpr int WMATB = 128 * RSB;
    constexpr int STG   = AMATB + WMATB;
    constexpr int NITER = ((BMT + 128) * 4) / 256;

    int bz = blockIdx.z;
    int s = (bz >= BB) ? 1 : 0;
    int b = bz & 3;
    int Mb = counts[b];
    int m0 = blockIdx.y * BMT;
    if (m0 >= Mb) return;
    int o0 = blockIdx.x * 128;
    const __half* Wsel = s ? Wbh : Wah;
    const float* bias = s ? bbv : ba;
    size_t rowbase = (size_t)(s*BB + b) * NT;
    const __half* Ah_g = Aall + (rowbase + m0) * K;
    const __half* Wh_g = Wsel + (size_t)o0 * K;
    float* Cfb = Cf ? Cf + rowbase * Ocols : (float*)0;
    __half* Chb = Ch ? Ch + rowbase * Ocols : (__half*)0;
    const float* Rb = R ? R + rowbase * Ocols : (const float*)0;

    extern __shared__ char smem[];
    uint32_t sbase = smem_u32(smem);
    int tid = threadIdx.x, lane = tid & 31, w = tid >> 5;
    int wm = w & 1, wn = w >> 1;
    int gid = lane >> 2, tig = lane & 3;

    float acc[MT][4][4];
    #pragma unroll
    for (int mt=0; mt<MT; mt++)
        #pragma unroll
        for (int nt=0; nt<4; nt++)
            #pragma unroll
            for (int q=0; q<4; q++) acc[mt][nt][q] = 0.f;

#define PREF16(cc, st) do { \
    uint32_t sb_ = sbase + (st)*STG; \
    _Pragma("unroll") \
    for (int i_ = 0; i_ < NITER; i_++) { \
        int f_ = tid + i_*256; int row_ = f_ >> 2; int jb_ = (f_ & 3) * 16; \
        const char* p_; uint32_t soff_; \
        if (row_ < BMT) { p_ = (const char*)(Ah_g + (size_t)row_*K + (size_t)(cc)*32); soff_ = (uint32_t)(row_*RSB); } \
        else            { int r_ = row_ - BMT; p_ = (const char*)(Wh_g + (size_t)r_*K + (size_t)(cc)*32); soff_ = (uint32_t)(AMATB + r_*RSB); } \
        CP16(sb_ + soff_ + jb_, p_ + jb_); \
    } } while (0)

    int nchunk = K >> 5;
    PREF16(0, 0);
    CPCOMMIT();
    if (nchunk > 1) { PREF16(1, 1); CPCOMMIT(); }

    for (int c = 0; c < nchunk; c++) {
        if (c == nchunk - 1) { CPWAIT(0); } else { CPWAIT(1); }
        __syncthreads();
        uint32_t stg = sbase + (c % 3) * STG;
        #pragma unroll
        for (int ks = 0; ks < 2; ks++) {
            uint32_t colb = (uint32_t)(ks*32 + ((lane >> 4) << 4));
            uint32_t Ahf[MT][4];
            #pragma unroll
            for (int mt = 0; mt < MT; mt++) {
                uint32_t sa = stg + (uint32_t)((wm*WMEXT + mt*16 + (lane & 15)) * RSB) + colb;
                LDSM4(Ahf[mt], sa);
            }
            #pragma unroll
            for (int np = 0; np < 2; np++) {
                uint32_t sb = stg + AMATB + (uint32_t)((wn*32 + np*16 + (lane & 15)) * RSB) + colb;
                uint32_t Bh[4];
                LDSM4(Bh, sb);
                #pragma unroll
                for (int mt = 0; mt < MT; mt++) {
                    mma16816h(acc[mt][2*np],   Ahf[mt], Bh[0], Bh[2]);
                    mma16816h(acc[mt][2*np+1], Ahf[mt], Bh[1], Bh[3]);
                }
            }
        }
        if (c + 2 < nchunk) { PREF16(c+2, (c+2) % 3); CPCOMMIT(); }
    }
#undef PREF16

    #pragma unroll
    for (int mt = 0; mt < MT; mt++) {
        int r0 = m0 + wm*WMEXT + mt*16 + gid;
        int r1 = r0 + 8;
        #pragma unroll
        for (int nt = 0; nt < 4; nt++) {
            int col = o0 + wn*32 + nt*8 + 2*tig;
            float b0v = bias[col], b1v = bias[col+1];
            float t0 = actf(acc[mt][nt][0] + b0v, act);
            float t1 = actf(acc[mt][nt][1] + b1v, act);
            float t2 = actf(acc[mt][nt][2] + b0v, act);
            float t3 = actf(acc[mt][nt][3] + b1v, act);
            if (Cfb) {
                if (r0 < Mb) {
                    if (Rb) { t0 += Rb[(size_t)r0*Ocols + col]; t1 += Rb[(size_t)r0*Ocols + col + 1]; }
                    *(float2*)&Cfb[(size_t)r0*Ocols + col] = make_float2(t0, t1);
                }
                if (r1 < Mb) {
                    if (Rb) { t2 += Rb[(size_t)r1*Ocols + col]; t3 += Rb[(size_t)r1*Ocols + col + 1]; }
                    *(float2*)&Cfb[(size_t)r1*Ocols + col] = make_float2(t2, t3);
                }
            } else {
                if (r0 < Mb) *(uint32_t*)&Chb[(size_t)r0*Ocols + col] = packh2(t0, t1);
                if (r1 < Mb) *(uint32_t*)&Chb[(size_t)r1*Ocols + col] = packh2(t2, t3);
            }
        }
    }
}

#define GEMM16_SMEM_128 (3*((128+128)*RSB))   // 61440
#define GEMM16_SMEM_64  (3*((64+128)*RSB))    // 46080

// ---------------- selection (from corrected logits) + inverse index ----------------
__global__ void select_kernel(const float* __restrict__ logits,
                              int* __restrict__ list, int* __restrict__ cnt,
                              float* __restrict__ maskf, int* __restrict__ iinv)
{
    int b = blockIdx.x, tid = threadIdx.x;
    const int PER = NT/256;  // 9
    __shared__ int cn[256];
    int base = tid*PER;
    float lv[PER];
    bool  sv[PER];
    int c = 0;
    #pragma unroll
    for (int i = 0; i < PER; i++) {
        float lg = logits[b*NT + base + i];
        lv[i] = lg;
        bool sel = lg > 0.f; sv[i] = sel; c += sel;
        maskf[b*NT + base + i] = sel ? 1.f : 0.f;
        iinv[b*NT + base + i] = -1;
    }
    cn[tid] = c; __syncthreads();
    for (int off = 1; off < 256; off <<= 1) {
        int v = (tid >= off) ? cn[tid-off] : 0;
        __syncthreads();
        cn[tid] += v;
        __syncthreads();
    }
    int total = cn[255];
    int pos = cn[tid] - c;
    if (total >= 64) {
        #pragma unroll
        for (int i = 0; i < PER; i++)
            if (sv[i]) { list[b*NT + pos] = base + i; iinv[b*NT + base + i] = pos; pos++; }
        if (tid == 0) cnt[b] = total;
    } else {
        __shared__ float sl[NT];
        #pragma unroll
        for (int i = 0; i < PER; i++) sl[base+i] = lv[i];
        __syncthreads();
        if (tid == 0) {
            for (int t = 0; t < 64; t++) {
                int am = 0; float mv = sl[0];
                for (int n = 1; n < NT; n++) if (sl[n] > mv) { mv = sl[n]; am = n; }
                list[b*NT + t] = am; iinv[b*NT + am] = t; sl[am] = -1e30f;
            }
            cnt[b] = 64;
        }
    }
}

// ---------------- fused gather + LayerNorm (both streams) -> fp16 ----------------
__global__ void gather_ln(const float* __restrict__ xcat, const int* __restrict__ list,
                          const int* __restrict__ cnt,
                          float* __restrict__ x, __half* __restrict__ Yh,
                          const float* __restrict__ ga, const float* __restrict__ bba,
                          const float* __restrict__ gb2, const float* __restrict__ bbb)
{
    int b = blockIdx.y, j = blockIdx.x;
    if (j >= cnt[b]) return;
    int idx = list[b*NT + j];
    int tid = threadIdx.x;
    const float* src = xcat + ((size_t)b*NT + idx)*512;
    __shared__ float red[8];
    #pragma unroll
    for (int s = 0; s < 2; s++) {
        const float* gw = s ? gb2 : ga;
        const float* gb = s ? bbb : bba;
        float v = src[s*CD + tid];
        size_t row = ((size_t)(s*BB + b)*NT + j)*CD;
        x[row + tid] = v;
        float ssum = v;
        #pragma unroll
        for (int o = 16; o; o >>= 1) ssum += __shfl_down_sync(0xffffffffu, ssum, o);
        if ((tid & 31) == 0) red[tid>>5] = ssum;
        __syncthreads();
        float mean = 0.f;
        #pragma unroll
        for (int i = 0; i < 8; i++) mean += red[i];
        mean *= (1.f/CD);
        __syncthreads();
        float d = v - mean;
        ssum = d*d;
        #pragma unroll
        for (int o = 16; o; o >>= 1) ssum += __shfl_down_sync(0xffffffffu, ssum, o);
        if ((tid & 31) == 0) red[tid>>5] = ssum;
        __syncthreads();
        float var = 0.f;
        #pragma unroll
        for (int i = 0; i < 8; i++) var += red[i];
        var *= (1.f/CD);
        Yh[row + tid] = __float2half_rn(d * rsqrtf(var + 1e-5f) * gw[tid] + gb[tid]);
        __syncthreads();
    }
}

// ---------------- LayerNorm (dual-stream) -> fp16 ----------------
__global__ void ln2(const float* __restrict__ X, __half* __restrict__ Yh,
                    const float* __restrict__ ga, const float* __restrict__ bba,
                    const float* __restrict__ gb2, const float* __restrict__ bbb,
                    const int* __restrict__ cnt)
{
    int bz = blockIdx.y; int s = bz >> 2, b = bz & 3;
    int n = blockIdx.x;
    if (n >= cnt[b]) return;
    const float* gw = s ? gb2 : ga;
    const float* gb = s ? bbb : bba;
    int tid = threadIdx.x;
    size_t row = ((size_t)(s*BB+b)*NT + n)*CD;
    float v = X[row + tid];
    __shared__ float red[8];
    float ssum = v;
    #pragma unroll
    for (int o = 16; o; o >>= 1) ssum += __shfl_down_sync(0xffffffffu, ssum, o);
    if ((tid & 31) == 0) red[tid>>5] = ssum;
    __syncthreads();
    float mean = 0.f;
    #pragma unroll
    for (int i = 0; i < 8; i++) mean += red[i];
    mean *= (1.f/CD);
    __syncthreads();
    float d = v - mean;
    ssum = d*d;
    #pragma unroll
    for (int o = 16; o; o >>= 1) ssum += __shfl_down_sync(0xffffffffu, ssum, o);
    if ((tid & 31) == 0) red[tid>>5] = ssum;
    __syncthreads();
    float var = 0.f;
    #pragma unroll
    for (int i = 0; i < 8; i++) var += red[i];
    var *= (1.f/CD);
    Yh[row + tid] = __float2half_rn(d * rsqrtf(var + 1e-5f) * gw[tid] + gb[tid]);
}

// ================= flash attention fp16 (single-term, hi-only), 3-stage, 2 CTAs/SM ======
#define AQR 144
#define AT_KVOFF (128*AQR)
#define AT_STG (2*64*AQR)
#define ATTN_SMEM (AT_KVOFF + 3*AT_STG)  // 73728

__global__ void __launch_bounds__(256, 2)
attn_mma(const __half* __restrict__ qkvh, __half* __restrict__ att_h,
         const int* __restrict__ cnt)
{
    extern __shared__ char smc[];
    uint32_t sb = smem_u32(smc);
    int bz = blockIdx.z; int s = bz >> 2, b = bz & 3;
    int h = blockIdx.y, q0 = blockIdx.x*128;
    int Mb = cnt[b];
    if (q0 >= Mb) return;
    int tid = threadIdx.x, lane = tid & 31, w = tid >> 5;
    int gid = lane >> 2, tig = lane & 3;
    size_t rowbase = (size_t)(s*BB + b) * NT;
    const __half* qg = qkvh;

    {
        #pragma unroll
        for (int i = 0; i < 4; i++) {
            int f = tid + i*256;
            int row = f >> 3, c16 = f & 7;
            const char* src = (const char*)(qg + (rowbase + q0 + row)*768 + h*64) + c16*16;
            CP16P(sb + row*AQR + c16*16, src, (q0 + row) < Mb);
        }
    }
#define KV_PREFETCH(kt, st) do { \
    int k0_ = (kt)*64; \
    _Pragma("unroll") \
    for (int i_ = 0; i_ < 4; i_++) { \
        int f_ = tid + i_*256; \
        int pl_ = f_ >> 9, rem_ = f_ & 511; \
        int row_ = rem_ >> 3, c16_ = rem_ & 7; \
        int ko_ = pl_ ? 512 : 256; \
        const char* src_ = (const char*)(qg + (rowbase + k0_ + row_)*768 + ko_ + h*64) + c16_*16; \
        uint32_t dst_ = sb + AT_KVOFF + (st)*AT_STG + pl_*(64*AQR) + row_*AQR + c16_*16; \
        CP16P(dst_, src_, (k0_ + row_) < Mb); \
    } } while (0)

    int nkt = (Mb + 63) >> 6;
    KV_PREFETCH(0, 0);
    CPCOMMIT();
    if (nkt > 1) { KV_PREFETCH(1, 1); CPCOMMIT(); }

    uint32_t Qh[4][4];
    float oacc[8][4];
    #pragma unroll
    for (int j=0;j<8;j++)
        #pragma unroll
        for (int q=0;q<4;q++) oacc[j][q] = 0.f;
    float l0 = 0.f, l1 = 0.f;
    bool qload = false;

    for (int c = 0; c < nkt; c++) {
        if (c == nkt - 1) { CPWAIT(0); } else { CPWAIT(1); }
        __syncthreads();
        if (!qload) {
            qload = true;
            #pragma unroll
            for (int ks = 0; ks < 4; ks++) {
                uint32_t qa = sb + (uint32_t)((w*16 + (lane & 15)) * AQR) + ks*32 + ((lane >> 4) << 4);
                LDSM4(Qh[ks], qa);
            }
        }
        uint32_t kb = sb + AT_KVOFF + (c % 3)*AT_STG;
        uint32_t vb = kb + 64*AQR;

        float sacc[8][4];
        #pragma unroll
        for (int j=0;j<8;j++)
            #pragma unroll
            for (int q=0;q<4;q++) sacc[j][q] = 0.f;
        #pragma unroll
        for (int ks = 0; ks < 4; ks++) {
            #pragma unroll
            for (int np = 0; np < 4; np++) {
                uint32_t ka = kb + (uint32_t)((np*16 + ((lane >> 4) << 3) + (lane & 7)) * AQR)
                            + ks*32 + (((lane >> 3) & 1) << 4);
                uint32_t Kh4[4];
                LDSM4(Kh4, ka);
                mma16816h(sacc[2*np],   Qh[ks], Kh4[0], Kh4[1]);
                mma16816h(sacc[2*np+1], Qh[ks], Kh4[2], Kh4[3]);
            }
        }
        int kvb = c*64;
        float s0 = 0.f, s1 = 0.f;
        #pragma unroll
        for (int j = 0; j < 8; j++) {
            int t0 = kvb + j*8 + 2*tig;
            bool v0 = t0 < Mb, v1 = (t0 + 1) < Mb;
            sacc[j][0] = v0 ? __expf(sacc[j][0]*0.125f) : 0.f;
            sacc[j][1] = v1 ? __expf(sacc[j][1]*0.125f) : 0.f;
            sacc[j][2] = v0 ? __expf(sacc[j][2]*0.125f) : 0.f;
            sacc[j][3] = v1 ? __expf(sacc[j][3]*0.125f) : 0.f;
            s0 += sacc[j][0] + sacc[j][1];
            s1 += sacc[j][2] + sacc[j][3];
        }
        s0 += __shfl_xor_sync(0xffffffffu, s0, 1);
        s0 += __shfl_xor_sync(0xffffffffu, s0, 2);
        s1 += __shfl_xor_sync(0xffffffffu, s1, 1);
        s1 += __shfl_xor_sync(0xffffffffu, s1, 2);
        l0 += s0; l1 += s1;
        #pragma unroll
        for (int kt = 0; kt < 4; kt++) {
            uint32_t aP[4];
            aP[0] = packh2(sacc[2*kt][0],   sacc[2*kt][1]);
            aP[1] = packh2(sacc[2*kt][2],   sacc[2*kt][3]);
            aP[2] = packh2(sacc[2*kt+1][0], sacc[2*kt+1][1]);
            aP[3] = packh2(sacc[2*kt+1][2], sacc[2*kt+1][3]);
            #pragma unroll
            for (int np = 0; np < 4; np++) {
                uint32_t va = vb + (uint32_t)((kt*16 + (((lane >> 3) & 1) << 3) + (lane & 7)) * AQR)
                            + (2*np + (lane >> 4))*16;
                uint32_t Vh4[4];
                LDSM4T(Vh4, va);
                mma16816h(oacc[2*np],   aP, Vh4[0], Vh4[1]);
                mma16816h(oacc[2*np+1], aP, Vh4[2], Vh4[3]);
            }
        }
        if (c + 2 < nkt) { KV_PREFETCH(c+2, (c+2) % 3); CPCOMMIT(); }
    }
#undef KV_PREFETCH

    float inv0 = 1.f / l0, inv1 = 1.f / l1;
    int qr0 = q0 + w*16 + gid;
    int qr1 = qr0 + 8;
    #pragma unroll
    for (int j = 0; j < 8; j++) {
        int col = h*64 + j*8 + 2*tig;
        if (qr0 < Mb)
            *(uint32_t*)&att_h[(rowbase + qr0)*CD + col] = packh2(oacc[j][0]*inv0, oacc[j][1]*inv0);
        if (qr1 < Mb)
            *(uint32_t*)&att_h[(rowbase + qr1)*CD + col] = packh2(oacc[j][2]*inv1, oacc[j][3]*inv1);
    }
}

// ---------------- fused output ----------------
__global__ void out_fuse(const float* __restrict__ fir, const float* __restrict__ fvis,
                         const float* __restrict__ x0, const float* __restrict__ x1,
                         const int* __restrict__ iinv, const float* __restrict__ maskf,
                         float* __restrict__ out)
{
    int b = blockIdx.z;
    int n0 = blockIdx.x*32, c0 = blockIdx.y*32;
    int tx = threadIdx.x, ty = threadIdx.y;
    __shared__ float tile[32][33];
    #pragma unroll
    for (int i = 0; i < 32; i += 8) {
        int n = n0 + ty + i;
        int j = iinv[b*NT + n];
        float v = 0.f;
        if (j >= 0) {
            float mv = maskf[b*NT + n];
            size_t r = ((size_t)b*NT + j)*CD + c0 + tx;
            v = (x0[r] + x1[r]) * mv;
        }
        tile[ty + i][tx] = v;
    }
    __syncthreads();
    #pragma unroll
    for (int i = 0; i < 32; i += 8) {
        int c = c0 + ty + i;
        int n = n0 + tx;
        size_t o = ((size_t)b*CD + c)*NT + n;
        int j = iinv[b*NT + n];
        float base = fir[o] + fvis[o];
        out[o] = (j >= 0) ? tile[tx][ty + i] : base;
    }
}

// ---------------- host ----------------
extern "C" void kernel_launch(void* const* d_in, const int* in_sizes, int n_in,
                              void* d_out, int out_size)
{
    const float* f_ir  = (const float*)d_in[0];
    const float* f_vis = (const float*)d_in[1];
    const float* aw1   = (const float*)d_in[2];
    const float* ab1   = (const float*)d_in[3];
    const float* aw2   = (const float*)d_in[4];
    const float* ab2   = (const float*)d_in[5];
    const float* ir_lng  = (const float*)d_in[6];
    const float* ir_lnb  = (const float*)d_in[7];
    const float* ir_wqkv = (const float*)d_in[8];
    const float* ir_bqkv = (const float*)d_in[9];
    const float* ir_wo   = (const float*)d_in[10];
    const float* ir_bo   = (const float*)d_in[11];
    const float* ir_w1   = (const float*)d_in[12];
    const float* ir_b1   = (const float*)d_in[13];
    const float* ir_w2   = (const float*)d_in[14];
    const float* ir_b2   = (const float*)d_in[15];
    const float* vi_lng  = (const float*)d_in[16];
    const float* vi_lnb  = (const float*)d_in[17];
    const float* vi_wqkv = (const float*)d_in[18];
    const float* vi_bqkv = (const float*)d_in[19];
    const float* vi_wo   = (const float*)d_in[20];
    const float* vi_bo   = (const float*)d_in[21];
    const float* vi_w1   = (const float*)d_in[22];
    const float* vi_b1   = (const float*)d_in[23];
    const float* vi_w2   = (const float*)d_in[24];
    const float* vi_b2   = (const float*)d_in[25];
    float* out = (float*)d_out;

    float *xcat,*partp,*logits,*maskf,*x;
    __half *xcath,*wag16,*w16,*xnh,*atth,*hidh,*qkvh;
    int *list,*iinv,*cntp;
    cudaGetSymbolAddress((void**)&xcat,  g_xcat);
    cudaGetSymbolAddress((void**)&partp, g_part);
    cudaGetSymbolAddress((void**)&logits,g_logits);
    cudaGetSymbolAddress((void**)&maskf, g_maskf);
    cudaGetSymbolAddress((void**)&x,     g_x);
    cudaGetSymbolAddress((void**)&xcath, g_xcat_h);
    cudaGetSymbolAddress((void**)&wag16, g_wag16);
    cudaGetSymbolAddress((void**)&w16,   g_w16);
    cudaGetSymbolAddress((void**)&xnh,   g_xn_h);
    cudaGetSymbolAddress((void**)&atth,  g_att_h);
    cudaGetSymbolAddress((void**)&hidh,  g_hid_h);
    cudaGetSymbolAddress((void**)&qkvh,  g_qkv_h);
    cudaGetSymbolAddress((void**)&list,  g_list);
    cudaGetSymbolAddress((void**)&iinv,  g_iinv);
    cudaGetSymbolAddress((void**)&cntp,  g_cnt);
    float* x0 = x;
    float* x1 = x + (size_t)BB*NT*CD;

    cudaFuncSetAttribute(attn_mma, cudaFuncAttributeMaxDynamicSharedMemorySize, ATTN_SMEM);
    cudaFuncSetAttribute(gemm_agent16, cudaFuncAttributeMaxDynamicSharedMemorySize, AGEMM_SMEM);
    cudaFuncSetAttribute(gemm_f16<128>, cudaFuncAttributeMaxDynamicSharedMemorySize, GEMM16_SMEM_128);
    cudaFuncSetAttribute(gemm_f16<64>,  cudaFuncAttributeMaxDynamicSharedMemorySize, GEMM16_SMEM_64);

    // weight conversions
    conv_wag16<<<64, 256>>>(aw1, wag16, 262144);
    W8 ws;
    const float* wsrc[8] = {ir_wqkv, vi_wqkv, ir_wo, vi_wo, ir_w1, vi_w1, ir_w2, vi_w2};
    const int    wn[8]   = {196608, 196608, 65536, 65536, 262144, 262144, 262144, 262144};
    int start = 0;
    for (int i = 0; i < 8; i++) { ws.src[i] = wsrc[i]; ws.n[i] = wn[i]; ws.start[i] = start; start += wn[i]; }
    conv_w16<<<dim3(64, 8), 256>>>(ws, w16);

    // 1. token-major concat (fp32 + fp16)
    transpose_cat<<<dim3(NT/32, CD/32, BB*2), dim3(32,8)>>>(f_ir, f_vis, xcat, xcath);
    // 2. agent GEMM (fp16 2-term) -> logit partials
    gemm_agent16<<<dim3(AGH/128, NT/128, BB), 256, AGEMM_SMEM>>>(
        xcath, wag16, 262144, ab1, aw2, partp);
    // 3. finalize logits + fp32 repair of near-zero logits
    repair<<<dim3(NT, BB), 256>>>(partp, ab2, xcat, aw1, ab1, aw2, logits);
    // 4. selection
    select_kernel<<<BB, 256>>>(logits, list, cntp, maskf, iinv);
    // 5. fused gather + first LN
    gather_ln<<<dim3(NT, BB), 256>>>(xcat, list, cntp, x, xnh,
                                     ir_lng, ir_lnb, vi_lng, vi_lnb);

    // 6. both mixers (fp16 single-term)
    gemm_f16<128><<<dim3(768/128, NT/128, 2*BB), 256, GEMM16_SMEM_128>>>(
        xnh, w16 + 0, w16 + 196608,
        ir_bqkv, vi_bqkv, (float*)0, qkvh, (const float*)0, cntp, 256, 768, 0);
    attn_mma<<<dim3(NT/128, NH, 2*BB), 256, ATTN_SMEM>>>(qkvh, atth, cntp);
    gemm_f16<64><<<dim3(CD/128, NT/64, 2*BB), 256, GEMM16_SMEM_64>>>(
        atth, w16 + 393216, w16 + 458752,
        ir_bo, vi_bo, x, (__half*)0, x, cntp, 256, CD, 0);
    ln2<<<dim3(NT, 2*BB), 256>>>(x, xnh, ir_lng, ir_lnb, vi_lng, vi_lnb, cntp);
    gemm_f16<128><<<dim3(1024/128, NT/128, 2*BB), 256, GEMM16_SMEM_128>>>(
        xnh, w16 + 524288, w16 + 786432,
        ir_b1, vi_b1, (float*)0, hidh, (const float*)0, cntp, 256, 1024, 2);
    gemm_f16<64><<<dim3(CD/128, NT/64, 2*BB), 256, GEMM16_SMEM_64>>>(
        hidh, w16 + 1048576, w16 + 1310720,
        ir_b2, vi_b2, x, (__half*)0, x, cntp, 1024, CD, 0);

    // 7. fused output
    out_fuse<<<dim3(NT/32, CD/32, BB), dim3(32,8)>>>(f_ir, f_vis, x0, x1, iinv, maskf, out);
}

// round 17
// speedup vs baseline: 2.6925x; 2.6925x over previous
#include <cuda_runtime.h>
#include <cuda_bf16.h>
#include <cuda_fp16.h>
#include <math.h>
#include <stdint.h>

#define BB   4
#define NT   2304      // 48*48 tokens
#define CD   256       // DIM
#define AGH  512       // agent hidden
#define NH   4
#define DH   64

// plane sizes (elements)
#define XCAT_PLANE ((size_t)BB*NT*512)
#define XN_PLANE   ((size_t)2*BB*NT*CD)
#define ATT_PLANE  ((size_t)2*BB*NT*CD)
#define HID_PLANE  ((size_t)2*BB*NT*1024)
#define QKV_PLANE  ((size_t)2*BB*NT*768)

// ---------------- HMMA m16n8k16 fp16 ----------------
__device__ __forceinline__ void mma16816h(float* c, const uint32_t* a, uint32_t b0, uint32_t b1) {
    asm volatile("mma.sync.aligned.m16n8k16.row.col.f32.f16.f16.f32 "
        "{%0,%1,%2,%3}, {%4,%5,%6,%7}, {%8,%9}, {%0,%1,%2,%3};"
        : "+f"(c[0]), "+f"(c[1]), "+f"(c[2]), "+f"(c[3])
        : "r"(a[0]), "r"(a[1]), "r"(a[2]), "r"(a[3]), "r"(b0), "r"(b1));
}

__device__ __forceinline__ uint32_t smem_u32(const void* p) {
    uint32_t a;
    asm("{ .reg .u64 t; cvta.to.shared.u64 t, %1; cvt.u32.u64 %0, t; }" : "=r"(a) : "l"(p));
    return a;
}
#define CP16(dst, src) asm volatile("cp.async.cg.shared.global [%0], [%1], 16;" :: "r"(dst), "l"(src))
#define CP16P(dst, src, p) asm volatile("cp.async.cg.shared.global [%0], [%1], 16, %2;" :: "r"(dst), "l"(src), "r"((p)?16:0))
#define CPCOMMIT()     asm volatile("cp.async.commit_group;" ::: "memory")
#define CPWAIT(n)      asm volatile("cp.async.wait_group %0;" :: "n"(n) : "memory")
#define LDSM4(r, a) asm volatile("ldmatrix.sync.aligned.m8n8.x4.shared.b16 {%0,%1,%2,%3}, [%4];" \
    : "=r"((r)[0]), "=r"((r)[1]), "=r"((r)[2]), "=r"((r)[3]) : "r"(a))
#define LDSM4T(r, a) asm volatile("ldmatrix.sync.aligned.m8n8.x4.trans.shared.b16 {%0,%1,%2,%3}, [%4];" \
    : "=r"((r)[0]), "=r"((r)[1]), "=r"((r)[2]), "=r"((r)[3]) : "r"(a))

// fp16 helpers
__device__ __forceinline__ uint32_t packh2(float a, float b) {
    __half2 h2 = __floats2half2_rn(a, b);
    return *reinterpret_cast<uint32_t*>(&h2);
}
__device__ __forceinline__ void pack_hl2h(float a, float b, uint32_t& ph, uint32_t& pl) {
    __half ha = __float2half_rn(a), hb = __float2half_rn(b);
    float la = a - __half2float(ha), lb = b - __half2float(hb);
    ph = ((uint32_t)__half_as_ushort(hb)<<16)|(uint32_t)__half_as_ushort(ha);
    pl = ((uint32_t)__half_as_ushort(__float2half_rn(lb))<<16)
       | (uint32_t)__half_as_ushort(__float2half_rn(la));
}

// ---------------- scratch ----------------
__device__ float g_xcat[(size_t)BB*NT*512];
__device__ float g_part[(size_t)BB*NT*4];
__device__ float g_logits[BB*NT];
__device__ float g_maskf [BB*NT];
__device__ int   g_list[BB*NT];
__device__ int   g_iinv[BB*NT];
__device__ int   g_cnt [BB];
__device__ float g_x  [(size_t)2*BB*NT*CD];
__device__ __align__(16) __half g_xcat_h[XCAT_PLANE];
__device__ __align__(16) __half g_wag16 [2*262144];        // agent aw1 hi/lo fp16
__device__ __align__(16) __half g_w16  [1572864];          // mixer weights hi only
__device__ __align__(16) __half g_xn_h [XN_PLANE];
__device__ __align__(16) __half g_att_h[ATT_PLANE];
__device__ __align__(16) __half g_hid_h[HID_PLANE];
__device__ __align__(16) __half g_qkv_h[QKV_PLANE];

// ---------------- weight converts ----------------
__global__ void conv_wag16(const float* __restrict__ src, __half* __restrict__ dst, int n)
{
    __half* dh = dst;
    __half* dl = dst + n;
    int n4 = n >> 2;
    for (int i = blockIdx.x*256 + threadIdx.x; i < n4; i += gridDim.x*256) {
        float4 v = ((const float4*)src)[i];
        uint32_t h0,l0,h1,l1;
        pack_hl2h(v.x, v.y, h0, l0);
        pack_hl2h(v.z, v.w, h1, l1);
        *(uint2*)&dh[i*4] = make_uint2(h0, h1);
        *(uint2*)&dl[i*4] = make_uint2(l0, l1);
    }
}
struct W8 { const float* src[8]; int start[8]; int n[8]; };
__global__ void conv_w16(W8 a, __half* __restrict__ dst)
{
    int w = blockIdx.y;
    int n = a.n[w];
    const float4* s = (const float4*)a.src[w];
    __half* dh = dst + a.start[w];
    int n4 = n >> 2;
    for (int i = blockIdx.x*256 + threadIdx.x; i < n4; i += gridDim.x*256) {
        float4 v = s[i];
        *(uint2*)&dh[i*4] = make_uint2(packh2(v.x, v.y), packh2(v.z, v.w));
    }
}

// ---------------- transpose [B,C,N] -> token-major concat fp32 + fp16 ----------------
__global__ void transpose_cat(const float* __restrict__ fir, const float* __restrict__ fvis,
                              float* __restrict__ xcat, __half* __restrict__ xcat_h)
{
    int src = blockIdx.z & 1;
    int b   = blockIdx.z >> 1;
    const float* f = src ? fvis : fir;
    __shared__ float tile[32][33];
    int n0 = blockIdx.x * 32, c0 = blockIdx.y * 32;
    int tx = threadIdx.x, ty = threadIdx.y;
    #pragma unroll
    for (int i = 0; i < 32; i += 8)
        tile[ty + i][tx] = f[((size_t)b*CD + c0 + ty + i)*NT + n0 + tx];
    __syncthreads();
    #pragma unroll
    for (int i = 0; i < 32; i += 8) {
        float v = tile[tx][ty + i];
        size_t idx = ((size_t)b*NT + n0 + ty + i)*512 + src*CD + c0 + tx;
        xcat[idx] = v;
        xcat_h[idx] = __float2half_rn(v);
    }
}

#define RSB   80
#define MATB  (128*RSB)

__device__ __forceinline__ float actf(float t, int act) {
    if (act == 1) return t / (1.f + expf(-t));
    if (act == 2) return 0.5f*t*(1.f + erff(t*0.70710678118654752f));
    return t;
}

// ======= agent GEMM: fp16 2-term (A hi, W hi+lo), logit partial epilogue =======
#define AG_STG (3*MATB)
#define AGEMM_SMEM (3*AG_STG)   // 92160
__global__ void __launch_bounds__(256, 2)
gemm_agent16(const __half* __restrict__ Ah, const __half* __restrict__ Whl, size_t wplane,
             const float* __restrict__ bias,
             const float* __restrict__ logit_w, float* __restrict__ part)
{
    const int K = 512;
    int b = blockIdx.z;
    int m0 = blockIdx.y * 128;
    int o0 = blockIdx.x * 128;
    size_t rowbase = (size_t)b * NT;
    const __half* Ah_g = Ah + (rowbase + m0) * K;
    const __half* Wh_g = Whl + (size_t)o0 * K;
    const __half* Wl_g = Wh_g + wplane;

    extern __shared__ char smem[];
    uint32_t sbase = smem_u32(smem);
    int tid = threadIdx.x, lane = tid & 31, w = tid >> 5;
    int wm = w & 1, wn = w >> 1;          // 2 m-warps (64 rows) x 4 n-warps (32 cols)
    int gid = lane >> 2, tig = lane & 3;

    float acc[4][4][4];
    #pragma unroll
    for (int mt=0; mt<4; mt++)
        #pragma unroll
        for (int nt=0; nt<4; nt++)
            #pragma unroll
            for (int q=0; q<4; q++) acc[mt][nt][q] = 0.f;

#define PREFAG(cc, st) do { \
    uint32_t sb_ = sbase + (st)*AG_STG; \
    _Pragma("unroll") \
    for (int i_ = 0; i_ < 6; i_++) { \
        int f_ = tid + i_*256; int mat_ = f_ >> 9; int rem_ = f_ & 511; \
        int row_ = rem_ >> 2; int jb_ = (rem_ & 3) * 16; \
        const char* p_ = (mat_ == 0) ? (const char*)(Ah_g + (size_t)row_*K + (size_t)(cc)*32) \
                       : (mat_ == 1) ? (const char*)(Wh_g + (size_t)row_*K + (size_t)(cc)*32) \
                                     : (const char*)(Wl_g + (size_t)row_*K + (size_t)(cc)*32); \
        CP16(sb_ + (uint32_t)(mat_*MATB + row_*RSB + jb_), p_ + jb_); \
    } } while (0)

    int nchunk = K >> 5;  // 16
    PREFAG(0, 0);
    CPCOMMIT();
    PREFAG(1, 1);
    CPCOMMIT();

    for (int c = 0; c < nchunk; c++) {
        if (c == nchunk - 1) { CPWAIT(0); } else { CPWAIT(1); }
        __syncthreads();
        uint32_t stg = sbase + (c % 3) * AG_STG;
        #pragma unroll
        for (int ks = 0; ks < 2; ks++) {
            uint32_t colb = (uint32_t)(ks*32 + ((lane >> 4) << 4));
            uint32_t Ahf[4][4];
            #pragma unroll
            for (int mt = 0; mt < 4; mt++) {
                uint32_t sa = stg + (uint32_t)((wm*64 + mt*16 + (lane & 15)) * RSB) + colb;
                LDSM4(Ahf[mt], sa);
            }
            #pragma unroll
            for (int np = 0; np < 2; np++) {
                uint32_t sb = stg + MATB + (uint32_t)((wn*32 + np*16 + (lane & 15)) * RSB) + colb;
                uint32_t Bh[4], Bl[4];
                LDSM4(Bh, sb);
                LDSM4(Bl, sb + MATB);
                #pragma unroll
                for (int mt = 0; mt < 4; mt++) {
                    mma16816h(acc[mt][2*np],   Ahf[mt], Bh[0], Bh[2]);
                    mma16816h(acc[mt][2*np+1], Ahf[mt], Bh[1], Bh[3]);
                }
                #pragma unroll
                for (int mt = 0; mt < 4; mt++) {
                    mma16816h(acc[mt][2*np],   Ahf[mt], Bl[0], Bl[2]);
                    mma16816h(acc[mt][2*np+1], Ahf[mt], Bl[1], Bl[3]);
                }
            }
        }
        if (c + 2 < nchunk) { PREFAG(c+2, (c+2) % 3); CPCOMMIT(); }
    }
#undef PREFAG

    // logit partials
    float pr[8];
    #pragma unroll
    for (int i = 0; i < 8; i++) pr[i] = 0.f;
    #pragma unroll
    for (int mt = 0; mt < 4; mt++) {
        #pragma unroll
        for (int nt = 0; nt < 4; nt++) {
            int col = o0 + wn*32 + nt*8 + 2*tig;
            float b0v = bias[col], b1v = bias[col+1];
            float w0 = logit_w[col], w1 = logit_w[col+1];
            float t0 = actf(acc[mt][nt][0] + b0v, 1);
            float t1 = actf(acc[mt][nt][1] + b1v, 1);
            float t2 = actf(acc[mt][nt][2] + b0v, 1);
            float t3 = actf(acc[mt][nt][3] + b1v, 1);
            pr[2*mt+0] += t0*w0 + t1*w1;
            pr[2*mt+1] += t2*w0 + t3*w1;
        }
    }
    #pragma unroll
    for (int i = 0; i < 8; i++) {
        pr[i] += __shfl_xor_sync(0xffffffffu, pr[i], 1);
        pr[i] += __shfl_xor_sync(0xffffffffu, pr[i], 2);
    }
    __syncthreads();
    float* red = (float*)smem;  // [4 wn][128 rows]
    if (tig == 0) {
        #pragma unroll
        for (int mt = 0; mt < 4; mt++) {
            red[wn*128 + wm*64 + mt*16 + gid]     = pr[2*mt+0];
            red[wn*128 + wm*64 + mt*16 + gid + 8] = pr[2*mt+1];
        }
    }
    __syncthreads();
    if (tid < 128)
        part[((size_t)b*NT + m0 + tid)*4 + blockIdx.x] =
            (red[tid] + red[128 + tid]) + (red[256 + tid] + red[384 + tid]);
}

// ---------------- repair v2: coalesced fp32 recompute of near-zero logits ----------------
#define REPAIR_TAU 1e-3f
__global__ void repair(const float* __restrict__ part, const float* __restrict__ ab2,
                       const float* __restrict__ xcat,
                       const float* __restrict__ aw1, const float* __restrict__ ab1,
                       const float* __restrict__ aw2, float* __restrict__ logits)
{
    int b = blockIdx.y, t = blockIdx.x;
    int tid = threadIdx.x, lane = tid & 31, w = tid >> 5;
    __shared__ float l_sh;
    if (tid == 0) {
        size_t t4 = ((size_t)b*NT + t)*4;
        l_sh = ((part[t4] + part[t4+1]) + (part[t4+2] + part[t4+3])) + ab2[0];
    }
    __syncthreads();
    float lg = l_sh;
    if (fabsf(lg) >= REPAIR_TAU) {
        if (tid == 0) logits[b*NT + t] = lg;
        return;
    }
    // exact fp32 recompute; warp-per-row, lanes stride k (coalesced), fixed order
    __shared__ float xs[512];
    const float* xr = xcat + ((size_t)b*NT + t)*512;
    for (int i = tid; i < 512; i += 256) xs[i] = xr[i];
    __syncthreads();
    float wacc = 0.f;
    for (int j = w*64; j < w*64 + 64; j++) {
        const float* wr = aw1 + (size_t)j*512;
        float s = 0.f;
        #pragma unroll 4
        for (int k = lane; k < 512; k += 32) s = fmaf(xs[k], wr[k], s);
        #pragma unroll
        for (int o = 16; o; o >>= 1) s += __shfl_down_sync(0xffffffffu, s, o);
        if (lane == 0) {
            s += ab1[j];
            float h = s / (1.f + expf(-s));
            wacc += h * aw2[j];
        }
    }
    __shared__ float wsum[8];
    if (lane == 0) wsum[w] = wacc;
    __syncthreads();
    if (tid == 0) {
        float tot = 0.f;
        for (int i = 0; i < 8; i++) tot += wsum[i];
        logits[b*NT + t] = tot + ab2[0];
    }
}

// ======= fp16 single-term GEMM (W hi only), BMT x 128 block, 3-stage, 2 CTAs/SM =======
template<int BMT>
__global__ void __launch_bounds__(256, 2)
gemm_f16(const __half* __restrict__ Aall,
         const __half* __restrict__ Wah, const __half* __restrict__ Wbh,
         const float* __restrict__ ba, const float* __restrict__ bbv,
         float* __restrict__ Cf, __half* __restrict__ Ch,
         const float* __restrict__ R,
         const int* __restrict__ counts, int K, int Ocols, int act)
{
    constexpr int NWM   = 2;
    constexpr int WMEXT = BMT / NWM;
    constexpr int MT    = WMEXT / 16;
    constexpr int AMATB = BMT * RSB;
    constexpr int WMATB = 128 * RSB;
    constexpr int STG   = AMATB + WMATB;
    constexpr int NITER = ((BMT + 128) * 4) / 256;

    int bz = blockIdx.z;
    int s = (bz >= BB) ? 1 : 0;
    int b = bz & 3;
    int Mb = counts[b];
    int m0 = blockIdx.y * BMT;
    if (m0 >= Mb) return;
    int o0 = blockIdx.x * 128;
    const __half* Wsel = s ? Wbh : Wah;
    const float* bias = s ? bbv : ba;
    size_t rowbase = (size_t)(s*BB + b) * NT;
    const __half* Ah_g = Aall + (rowbase + m0) * K;
    const __half* Wh_g = Wsel + (size_t)o0 * K;
    float* Cfb = Cf ? Cf + rowbase * Ocols : (float*)0;
    __half* Chb = Ch ? Ch + rowbase * Ocols : (__half*)0;
    const float* Rb = R ? R + rowbase * Ocols : (const float*)0;

    extern __shared__ char smem[];
    uint32_t sbase = smem_u32(smem);
    int tid = threadIdx.x, lane = tid & 31, w = tid >> 5;
    int wm = w & 1, wn = w >> 1;
    int gid = lane >> 2, tig = lane & 3;

    float acc[MT][4][4];
    #pragma unroll
    for (int mt=0; mt<MT; mt++)
        #pragma unroll
        for (int nt=0; nt<4; nt++)
            #pragma unroll
            for (int q=0; q<4; q++) acc[mt][nt][q] = 0.f;

#define PREF16(cc, st) do { \
    uint32_t sb_ = sbase + (st)*STG; \
    _Pragma("unroll") \
    for (int i_ = 0; i_ < NITER; i_++) { \
        int f_ = tid + i_*256; int row_ = f_ >> 2; int jb_ = (f_ & 3) * 16; \
        const char* p_; uint32_t soff_; \
        if (row_ < BMT) { p_ = (const char*)(Ah_g + (size_t)row_*K + (size_t)(cc)*32); soff_ = (uint32_t)(row_*RSB); } \
        else            { int r_ = row_ - BMT; p_ = (const char*)(Wh_g + (size_t)r_*K + (size_t)(cc)*32); soff_ = (uint32_t)(AMATB + r_*RSB); } \
        CP16(sb_ + soff_ + jb_, p_ + jb_); \
    } } while (0)

    int nchunk = K >> 5;
    PREF16(0, 0);
    CPCOMMIT();
    if (nchunk > 1) { PREF16(1, 1); CPCOMMIT(); }

    for (int c = 0; c < nchunk; c++) {
        if (c == nchunk - 1) { CPWAIT(0); } else { CPWAIT(1); }
        __syncthreads();
        uint32_t stg = sbase + (c % 3) * STG;
        #pragma unroll
        for (int ks = 0; ks < 2; ks++) {
            uint32_t colb = (uint32_t)(ks*32 + ((lane >> 4) << 4));
            uint32_t Ahf[MT][4];
            #pragma unroll
            for (int mt = 0; mt < MT; mt++) {
                uint32_t sa = stg + (uint32_t)((wm*WMEXT + mt*16 + (lane & 15)) * RSB) + colb;
                LDSM4(Ahf[mt], sa);
            }
            #pragma unroll
            for (int np = 0; np < 2; np++) {
                uint32_t sb = stg + AMATB + (uint32_t)((wn*32 + np*16 + (lane & 15)) * RSB) + colb;
                uint32_t Bh[4];
                LDSM4(Bh, sb);
                #pragma unroll
                for (int mt = 0; mt < MT; mt++) {
                    mma16816h(acc[mt][2*np],   Ahf[mt], Bh[0], Bh[2]);
                    mma16816h(acc[mt][2*np+1], Ahf[mt], Bh[1], Bh[3]);
                }
            }
        }
        if (c + 2 < nchunk) { PREF16(c+2, (c+2) % 3); CPCOMMIT(); }
    }
#undef PREF16

    #pragma unroll
    for (int mt = 0; mt < MT; mt++) {
        int r0 = m0 + wm*WMEXT + mt*16 + gid;
        int r1 = r0 + 8;
        #pragma unroll
        for (int nt = 0; nt < 4; nt++) {
            int col = o0 + wn*32 + nt*8 + 2*tig;
            float b0v = bias[col], b1v = bias[col+1];
            float t0 = actf(acc[mt][nt][0] + b0v, act);
            float t1 = actf(acc[mt][nt][1] + b1v, act);
            float t2 = actf(acc[mt][nt][2] + b0v, act);
            float t3 = actf(acc[mt][nt][3] + b1v, act);
            if (Cfb) {
                if (r0 < Mb) {
                    if (Rb) { t0 += Rb[(size_t)r0*Ocols + col]; t1 += Rb[(size_t)r0*Ocols + col + 1]; }
                    *(float2*)&Cfb[(size_t)r0*Ocols + col] = make_float2(t0, t1);
                }
                if (r1 < Mb) {
                    if (Rb) { t2 += Rb[(size_t)r1*Ocols + col]; t3 += Rb[(size_t)r1*Ocols + col + 1]; }
                    *(float2*)&Cfb[(size_t)r1*Ocols + col] = make_float2(t2, t3);
                }
            } else {
                if (r0 < Mb) *(uint32_t*)&Chb[(size_t)r0*Ocols + col] = packh2(t0, t1);
                if (r1 < Mb) *(uint32_t*)&Chb[(size_t)r1*Ocols + col] = packh2(t2, t3);
            }
        }
    }
}

#define GEMM16_SMEM_128 (3*((128+128)*RSB))   // 61440
#define GEMM16_SMEM_64  (3*((64+128)*RSB))    // 46080

// ---------------- selection (from corrected logits) + inverse index ----------------
__global__ void select_kernel(const float* __restrict__ logits,
                              int* __restrict__ list, int* __restrict__ cnt,
                              float* __restrict__ maskf, int* __restrict__ iinv)
{
    int b = blockIdx.x, tid = threadIdx.x;
    const int PER = NT/256;  // 9
    __shared__ int cn[256];
    int base = tid*PER;
    float lv[PER];
    bool  sv[PER];
    int c = 0;
    #pragma unroll
    for (int i = 0; i < PER; i++) {
        float lg = logits[b*NT + base + i];
        lv[i] = lg;
        bool sel = lg > 0.f; sv[i] = sel; c += sel;
        maskf[b*NT + base + i] = sel ? 1.f : 0.f;
        iinv[b*NT + base + i] = -1;
    }
    cn[tid] = c; __syncthreads();
    for (int off = 1; off < 256; off <<= 1) {
        int v = (tid >= off) ? cn[tid-off] : 0;
        __syncthreads();
        cn[tid] += v;
        __syncthreads();
    }
    int total = cn[255];
    int pos = cn[tid] - c;
    if (total >= 64) {
        #pragma unroll
        for (int i = 0; i < PER; i++)
            if (sv[i]) { list[b*NT + pos] = base + i; iinv[b*NT + base + i] = pos; pos++; }
        if (tid == 0) cnt[b] = total;
    } else {
        __shared__ float sl[NT];
        #pragma unroll
        for (int i = 0; i < PER; i++) sl[base+i] = lv[i];
        __syncthreads();
        if (tid == 0) {
            for (int t = 0; t < 64; t++) {
                int am = 0; float mv = sl[0];
                for (int n = 1; n < NT; n++) if (sl[n] > mv) { mv = sl[n]; am = n; }
                list[b*NT + t] = am; iinv[b*NT + am] = t; sl[am] = -1e30f;
            }
            cnt[b] = 64;
        }
    }
}

// ---------------- fused gather + LayerNorm (both streams) -> fp16 ----------------
__global__ void gather_ln(const float* __restrict__ xcat, const int* __restrict__ list,
                          const int* __restrict__ cnt,
                          float* __restrict__ x, __half* __restrict__ Yh,
                          const float* __restrict__ ga, const float* __restrict__ bba,
                          const float* __restrict__ gb2, const float* __restrict__ bbb)
{
    int b = blockIdx.y, j = blockIdx.x;
    if (j >= cnt[b]) return;
    int idx = list[b*NT + j];
    int tid = threadIdx.x;
    const float* src = xcat + ((size_t)b*NT + idx)*512;
    __shared__ float red[8];
    #pragma unroll
    for (int s = 0; s < 2; s++) {
        const float* gw = s ? gb2 : ga;
        const float* gb = s ? bbb : bba;
        float v = src[s*CD + tid];
        size_t row = ((size_t)(s*BB + b)*NT + j)*CD;
        x[row + tid] = v;
        float ssum = v;
        #pragma unroll
        for (int o = 16; o; o >>= 1) ssum += __shfl_down_sync(0xffffffffu, ssum, o);
        if ((tid & 31) == 0) red[tid>>5] = ssum;
        __syncthreads();
        float mean = 0.f;
        #pragma unroll
        for (int i = 0; i < 8; i++) mean += red[i];
        mean *= (1.f/CD);
        __syncthreads();
        float d = v - mean;
        ssum = d*d;
        #pragma unroll
        for (int o = 16; o; o >>= 1) ssum += __shfl_down_sync(0xffffffffu, ssum, o);
        if ((tid & 31) == 0) red[tid>>5] = ssum;
        __syncthreads();
        float var = 0.f;
        #pragma unroll
        for (int i = 0; i < 8; i++) var += red[i];
        var *= (1.f/CD);
        Yh[row + tid] = __float2half_rn(d * rsqrtf(var + 1e-5f) * gw[tid] + gb[tid]);
        __syncthreads();
    }
}

// ---------------- LayerNorm (dual-stream) -> fp16 ----------------
__global__ void ln2(const float* __restrict__ X, __half* __restrict__ Yh,
                    const float* __restrict__ ga, const float* __restrict__ bba,
                    const float* __restrict__ gb2, const float* __restrict__ bbb,
                    const int* __restrict__ cnt)
{
    int bz = blockIdx.y; int s = bz >> 2, b = bz & 3;
    int n = blockIdx.x;
    if (n >= cnt[b]) return;
    const float* gw = s ? gb2 : ga;
    const float* gb = s ? bbb : bba;
    int tid = threadIdx.x;
    size_t row = ((size_t)(s*BB+b)*NT + n)*CD;
    float v = X[row + tid];
    __shared__ float red[8];
    float ssum = v;
    #pragma unroll
    for (int o = 16; o; o >>= 1) ssum += __shfl_down_sync(0xffffffffu, ssum, o);
    if ((tid & 31) == 0) red[tid>>5] = ssum;
    __syncthreads();
    float mean = 0.f;
    #pragma unroll
    for (int i = 0; i < 8; i++) mean += red[i];
    mean *= (1.f/CD);
    __syncthreads();
    float d = v - mean;
    ssum = d*d;
    #pragma unroll
    for (int o = 16; o; o >>= 1) ssum += __shfl_down_sync(0xffffffffu, ssum, o);
    if ((tid & 31) == 0) red[tid>>5] = ssum;
    __syncthreads();
    float var = 0.f;
    #pragma unroll
    for (int i = 0; i < 8; i++) var += red[i];
    var *= (1.f/CD);
    Yh[row + tid] = __float2half_rn(d * rsqrtf(var + 1e-5f) * gw[tid] + gb[tid]);
}

// ================= flash attention fp16 (single-term, hi-only), 3-stage, 2 CTAs/SM ======
#define AQR 144
#define AT_KVOFF (128*AQR)
#define AT_STG (2*64*AQR)
#define ATTN_SMEM (AT_KVOFF + 3*AT_STG)  // 73728

__global__ void __launch_bounds__(256, 2)
attn_mma(const __half* __restrict__ qkvh, __half* __restrict__ att_h,
         const int* __restrict__ cnt)
{
    extern __shared__ char smc[];
    uint32_t sb = smem_u32(smc);
    int bz = blockIdx.z; int s = bz >> 2, b = bz & 3;
    int h = blockIdx.y, q0 = blockIdx.x*128;
    int Mb = cnt[b];
    if (q0 >= Mb) return;
    int tid = threadIdx.x, lane = tid & 31, w = tid >> 5;
    int gid = lane >> 2, tig = lane & 3;
    size_t rowbase = (size_t)(s*BB + b) * NT;
    const __half* qg = qkvh;

    {
        #pragma unroll
        for (int i = 0; i < 4; i++) {
            int f = tid + i*256;
            int row = f >> 3, c16 = f & 7;
            const char* src = (const char*)(qg + (rowbase + q0 + row)*768 + h*64) + c16*16;
            CP16P(sb + row*AQR + c16*16, src, (q0 + row) < Mb);
        }
    }
#define KV_PREFETCH(kt, st) do { \
    int k0_ = (kt)*64; \
    _Pragma("unroll") \
    for (int i_ = 0; i_ < 4; i_++) { \
        int f_ = tid + i_*256; \
        int pl_ = f_ >> 9, rem_ = f_ & 511; \
        int row_ = rem_ >> 3, c16_ = rem_ & 7; \
        int ko_ = pl_ ? 512 : 256; \
        const char* src_ = (const char*)(qg + (rowbase + k0_ + row_)*768 + ko_ + h*64) + c16_*16; \
        uint32_t dst_ = sb + AT_KVOFF + (st)*AT_STG + pl_*(64*AQR) + row_*AQR + c16_*16; \
        CP16P(dst_, src_, (k0_ + row_) < Mb); \
    } } while (0)

    int nkt = (Mb + 63) >> 6;
    KV_PREFETCH(0, 0);
    CPCOMMIT();
    if (nkt > 1) { KV_PREFETCH(1, 1); CPCOMMIT(); }

    uint32_t Qh[4][4];
    float oacc[8][4];
    #pragma unroll
    for (int j=0;j<8;j++)
        #pragma unroll
        for (int q=0;q<4;q++) oacc[j][q] = 0.f;
    float l0 = 0.f, l1 = 0.f;
    bool qload = false;

    for (int c = 0; c < nkt; c++) {
        if (c == nkt - 1) { CPWAIT(0); } else { CPWAIT(1); }
        __syncthreads();
        if (!qload) {
            qload = true;
            #pragma unroll
            for (int ks = 0; ks < 4; ks++) {
                uint32_t qa = sb + (uint32_t)((w*16 + (lane & 15)) * AQR) + ks*32 + ((lane >> 4) << 4);
                LDSM4(Qh[ks], qa);
            }
        }
        uint32_t kb = sb + AT_KVOFF + (c % 3)*AT_STG;
        uint32_t vb = kb + 64*AQR;

        float sacc[8][4];
        #pragma unroll
        for (int j=0;j<8;j++)
            #pragma unroll
            for (int q=0;q<4;q++) sacc[j][q] = 0.f;
        #pragma unroll
        for (int ks = 0; ks < 4; ks++) {
            #pragma unroll
            for (int np = 0; np < 4; np++) {
                uint32_t ka = kb + (uint32_t)((np*16 + ((lane >> 4) << 3) + (lane & 7)) * AQR)
                            + ks*32 + (((lane >> 3) & 1) << 4);
                uint32_t Kh4[4];
                LDSM4(Kh4, ka);
                mma16816h(sacc[2*np],   Qh[ks], Kh4[0], Kh4[1]);
                mma16816h(sacc[2*np+1], Qh[ks], Kh4[2], Kh4[3]);
            }
        }
        int kvb = c*64;
        float s0 = 0.f, s1 = 0.f;
        #pragma unroll
        for (int j = 0; j < 8; j++) {
            int t0 = kvb + j*8 + 2*tig;
            bool v0 = t0 < Mb, v1 = (t0 + 1) < Mb;
            sacc[j][0] = v0 ? __expf(sacc[j][0]*0.125f) : 0.f;
            sacc[j][1] = v1 ? __expf(sacc[j][1]*0.125f) : 0.f;
            sacc[j][2] = v0 ? __expf(sacc[j][2]*0.125f) : 0.f;
            sacc[j][3] = v1 ? __expf(sacc[j][3]*0.125f) : 0.f;
            s0 += sacc[j][0] + sacc[j][1];
            s1 += sacc[j][2] + sacc[j][3];
        }
        s0 += __shfl_xor_sync(0xffffffffu, s0, 1);
        s0 += __shfl_xor_sync(0xffffffffu, s0, 2);
        s1 += __shfl_xor_sync(0xffffffffu, s1, 1);
        s1 += __shfl_xor_sync(0xffffffffu, s1, 2);
        l0 += s0; l1 += s1;
        #pragma unroll
        for (int kt = 0; kt < 4; kt++) {
            uint32_t aP[4];
            aP[0] = packh2(sacc[2*kt][0],   sacc[2*kt][1]);
            aP[1] = packh2(sacc[2*kt][2],   sacc[2*kt][3]);
            aP[2] = packh2(sacc[2*kt+1][0], sacc[2*kt+1][1]);
            aP[3] = packh2(sacc[2*kt+1][2], sacc[2*kt+1][3]);
            #pragma unroll
            for (int np = 0; np < 4; np++) {
                uint32_t va = vb + (uint32_t)((kt*16 + (((lane >> 3) & 1) << 3) + (lane & 7)) * AQR)
                            + (2*np + (lane >> 4))*16;
                uint32_t Vh4[4];
                LDSM4T(Vh4, va);
                mma16816h(oacc[2*np],   aP, Vh4[0], Vh4[1]);
                mma16816h(oacc[2*np+1], aP, Vh4[2], Vh4[3]);
            }
        }
        if (c + 2 < nkt) { KV_PREFETCH(c+2, (c+2) % 3); CPCOMMIT(); }
    }
#undef KV_PREFETCH

    float inv0 = 1.f / l0, inv1 = 1.f / l1;
    int qr0 = q0 + w*16 + gid;
    int qr1 = qr0 + 8;
    #pragma unroll
    for (int j = 0; j < 8; j++) {
        int col = h*64 + j*8 + 2*tig;
        if (qr0 < Mb)
            *(uint32_t*)&att_h[(rowbase + qr0)*CD + col] = packh2(oacc[j][0]*inv0, oacc[j][1]*inv0);
        if (qr1 < Mb)
            *(uint32_t*)&att_h[(rowbase + qr1)*CD + col] = packh2(oacc[j][2]*inv1, oacc[j][3]*inv1);
    }
}

// ---------------- fused output ----------------
__global__ void out_fuse(const float* __restrict__ fir, const float* __restrict__ fvis,
                         const float* __restrict__ x0, const float* __restrict__ x1,
                         const int* __restrict__ iinv, const float* __restrict__ maskf,
                         float* __restrict__ out)
{
    int b = blockIdx.z;
    int n0 = blockIdx.x*32, c0 = blockIdx.y*32;
    int tx = threadIdx.x, ty = threadIdx.y;
    __shared__ float tile[32][33];
    #pragma unroll
    for (int i = 0; i < 32; i += 8) {
        int n = n0 + ty + i;
        int j = iinv[b*NT + n];
        float v = 0.f;
        if (j >= 0) {
            float mv = maskf[b*NT + n];
            size_t r = ((size_t)b*NT + j)*CD + c0 + tx;
            v = (x0[r] + x1[r]) * mv;
        }
        tile[ty + i][tx] = v;
    }
    __syncthreads();
    #pragma unroll
    for (int i = 0; i < 32; i += 8) {
        int c = c0 + ty + i;
        int n = n0 + tx;
        size_t o = ((size_t)b*CD + c)*NT + n;
        int j = iinv[b*NT + n];
        float base = fir[o] + fvis[o];
        out[o] = (j >= 0) ? tile[tx][ty + i] : base;
    }
}

// ---------------- host ----------------
extern "C" void kernel_launch(void* const* d_in, const int* in_sizes, int n_in,
                              void* d_out, int out_size)
{
    const float* f_ir  = (const float*)d_in[0];
    const float* f_vis = (const float*)d_in[1];
    const float* aw1   = (const float*)d_in[2];
    const float* ab1   = (const float*)d_in[3];
    const float* aw2   = (const float*)d_in[4];
    const float* ab2   = (const float*)d_in[5];
    const float* ir_lng  = (const float*)d_in[6];
    const float* ir_lnb  = (const float*)d_in[7];
    const float* ir_wqkv = (const float*)d_in[8];
    const float* ir_bqkv = (const float*)d_in[9];
    const float* ir_wo   = (const float*)d_in[10];
    const float* ir_bo   = (const float*)d_in[11];
    const float* ir_w1   = (const float*)d_in[12];
    const float* ir_b1   = (const float*)d_in[13];
    const float* ir_w2   = (const float*)d_in[14];
    const float* ir_b2   = (const float*)d_in[15];
    const float* vi_lng  = (const float*)d_in[16];
    const float* vi_lnb  = (const float*)d_in[17];
    const float* vi_wqkv = (const float*)d_in[18];
    const float* vi_bqkv = (const float*)d_in[19];
    const float* vi_wo   = (const float*)d_in[20];
    const float* vi_bo   = (const float*)d_in[21];
    const float* vi_w1   = (const float*)d_in[22];
    const float* vi_b1   = (const float*)d_in[23];
    const float* vi_w2   = (const float*)d_in[24];
    const float* vi_b2   = (const float*)d_in[25];
    float* out = (float*)d_out;

    float *xcat,*partp,*logits,*maskf,*x;
    __half *xcath,*wag16,*w16,*xnh,*atth,*hidh,*qkvh;
    int *list,*iinv,*cntp;
    cudaGetSymbolAddress((void**)&xcat,  g_xcat);
    cudaGetSymbolAddress((void**)&partp, g_part);
    cudaGetSymbolAddress((void**)&logits,g_logits);
    cudaGetSymbolAddress((void**)&maskf, g_maskf);
    cudaGetSymbolAddress((void**)&x,     g_x);
    cudaGetSymbolAddress((void**)&xcath, g_xcat_h);
    cudaGetSymbolAddress((void**)&wag16, g_wag16);
    cudaGetSymbolAddress((void**)&w16,   g_w16);
    cudaGetSymbolAddress((void**)&xnh,   g_xn_h);
    cudaGetSymbolAddress((void**)&atth,  g_att_h);
    cudaGetSymbolAddress((void**)&hidh,  g_hid_h);
    cudaGetSymbolAddress((void**)&qkvh,  g_qkv_h);
    cudaGetSymbolAddress((void**)&list,  g_list);
    cudaGetSymbolAddress((void**)&iinv,  g_iinv);
    cudaGetSymbolAddress((void**)&cntp,  g_cnt);
    float* x0 = x;
    float* x1 = x + (size_t)BB*NT*CD;

    cudaFuncSetAttribute(attn_mma, cudaFuncAttributeMaxDynamicSharedMemorySize, ATTN_SMEM);
    cudaFuncSetAttribute(gemm_agent16, cudaFuncAttributeMaxDynamicSharedMemorySize, AGEMM_SMEM);
    cudaFuncSetAttribute(gemm_f16<128>, cudaFuncAttributeMaxDynamicSharedMemorySize, GEMM16_SMEM_128);
    cudaFuncSetAttribute(gemm_f16<64>,  cudaFuncAttributeMaxDynamicSharedMemorySize, GEMM16_SMEM_64);

    // weight conversions
    conv_wag16<<<64, 256>>>(aw1, wag16, 262144);
    W8 ws;
    const float* wsrc[8] = {ir_wqkv, vi_wqkv, ir_wo, vi_wo, ir_w1, vi_w1, ir_w2, vi_w2};
    const int    wn[8]   = {196608, 196608, 65536, 65536, 262144, 262144, 262144, 262144};
    int start = 0;
    for (int i = 0; i < 8; i++) { ws.src[i] = wsrc[i]; ws.n[i] = wn[i]; ws.start[i] = start; start += wn[i]; }
    conv_w16<<<dim3(64, 8), 256>>>(ws, w16);

    // 1. token-major concat (fp32 + fp16)
    transpose_cat<<<dim3(NT/32, CD/32, BB*2), dim3(32,8)>>>(f_ir, f_vis, xcat, xcath);
    // 2. agent GEMM (fp16 2-term) -> logit partials
    gemm_agent16<<<dim3(AGH/128, NT/128, BB), 256, AGEMM_SMEM>>>(
        xcath, wag16, 262144, ab1, aw2, partp);
    // 3. finalize logits + coalesced fp32 repair of near-zero logits
    repair<<<dim3(NT, BB), 256>>>(partp, ab2, xcat, aw1, ab1, aw2, logits);
    // 4. selection
    select_kernel<<<BB, 256>>>(logits, list, cntp, maskf, iinv);
    // 5. fused gather + first LN
    gather_ln<<<dim3(NT, BB), 256>>>(xcat, list, cntp, x, xnh,
                                     ir_lng, ir_lnb, vi_lng, vi_lnb);

    // 6. both mixers (fp16 single-term)
    gemm_f16<128><<<dim3(768/128, NT/128, 2*BB), 256, GEMM16_SMEM_128>>>(
        xnh, w16 + 0, w16 + 196608,
        ir_bqkv, vi_bqkv, (float*)0, qkvh, (const float*)0, cntp, 256, 768, 0);
    attn_mma<<<dim3(NT/128, NH, 2*BB), 256, ATTN_SMEM>>>(qkvh, atth, cntp);
    gemm_f16<64><<<dim3(CD/128, NT/64, 2*BB), 256, GEMM16_SMEM_64>>>(
        atth, w16 + 393216, w16 + 458752,
        ir_bo, vi_bo, x, (__half*)0, x, cntp, 256, CD, 0);
    ln2<<<dim3(NT, 2*BB), 256>>>(x, xnh, ir_lng, ir_lnb, vi_lng, vi_lnb, cntp);
    gemm_f16<128><<<dim3(1024/128, NT/128, 2*BB), 256, GEMM16_SMEM_128>>>(
        xnh, w16 + 524288, w16 + 786432,
        ir_b1, vi_b1, (float*)0, hidh, (const float*)0, cntp, 256, 1024, 2);
    gemm_f16<64><<<dim3(CD/128, NT/64, 2*BB), 256, GEMM16_SMEM_64>>>(
        hidh, w16 + 1048576, w16 + 1310720,
        ir_b2, vi_b2, x, (__half*)0, x, cntp, 1024, CD, 0);

    // 7. fused output
    out_fuse<<<dim3(NT/32, CD/32, BB), dim3(32,8)>>>(f_ir, f_vis, x0, x1, iinv, maskf, out);
}